// round 6
// baseline (speedup 1.0000x reference)
#include <cuda_runtime.h>
#include <cstdint>

// DeepMapping2D occupancy_generation, GB300 sm_103a.  Round 6.
//
//   output[b] = K_b ones then zeros, K_b = #bins with count >= 53.
//   Min-shift is a bin bijection -> K_b shift-invariant -> no min pass.
//
// Model (validated R4/R5): hist is pinned at the LTS cap -- 16.7M byte-RMWs
// x ~64B sector traffic ~= 1.07GB ~= 95us. Per-thread MLP beyond the R4
// shape HURTS (R5: regs 40, occ 64%, +3us). So:
//   * hist reverts to the R4 loop shape (regs ~22, occ 90%), but uses
//     atomicAdd WITH return (ATOMG == REDG at the LTS per quickref): the
//     old byte == 52 exactly at the 52->53 crossing, giving K_b inline and
//     DELETING the 13us count pass entirely.
//   * trailing kernel (proven R5): pure-store re-zero + output expansion
//     + counter reset.  2 launches total.

#define NBATCH  64
#define NPTS    262144
#define TOPK    5120
#define GZ_LOG2 10
#define BINS_PER_BATCH   (1024u * 1024u)          // 1M u8 bins / batch
#define HWORDS_PER_BATCH (BINS_PER_BATCH / 4)     // 256K u32 / batch

__device__ unsigned int g_hist[(size_t)NBATCH * HWORDS_PER_BATCH];  // 64 MB, load-zeroed
__device__ unsigned int g_count[NBATCH];                            // load-zeroed

// ---------------------------------------------------------------------------
// Kernel 1: histogram scatter + inline occupied-bin detection.
// grid (64, 64) x 256 thr; grid-stride loop, 8 iters x 2 points.
// Each atomicAdd returns the old word; old byte == 52 marks the unique
// 52->53 crossing of that bin.
// ---------------------------------------------------------------------------
__global__ void dm2d_hist_kernel(const float4* __restrict__ pcd) {
    const int b = blockIdx.y;
    unsigned int* __restrict__ hist = g_hist + (size_t)b * HWORDS_PER_BATCH;
    const float4* __restrict__ base = pcd + (size_t)b * (NPTS / 2);

    const int tid    = blockIdx.x * blockDim.x + threadIdx.x;
    const int stride = gridDim.x * blockDim.x;

    unsigned int local = 0;
    #pragma unroll 4
    for (int i = tid; i < NPTS / 2; i += stride) {
        float4 p = __ldcs(&base[i]);   // two points: (x0,z0,x1,z1); evict-first

        // jnp.round = round-half-to-even == rintf under default RN mode.
        unsigned x0 = (unsigned)(int)rintf(1000.0f * p.x);
        unsigned z0 = (unsigned)(int)rintf(1000.0f * p.y);
        unsigned x1 = (unsigned)(int)rintf(1000.0f * p.z);
        unsigned z1 = (unsigned)(int)rintf(1000.0f * p.w);

        unsigned i0 = (x0 << GZ_LOG2) | z0;
        unsigned i1 = (x1 << GZ_LOG2) | z1;

        unsigned s0 = (i0 & 3u) << 3;
        unsigned s1 = (i1 & 3u) << 3;
        unsigned o0 = atomicAdd(&hist[i0 >> 2], 1u << s0);
        unsigned o1 = atomicAdd(&hist[i1 >> 2], 1u << s1);
        local += (((o0 >> s0) & 0xFFu) == 52u);
        local += (((o1 >> s1) & 0xFFu) == 52u);
    }

    // warp reduce; with this input local is almost always 0 -> near-free.
    #pragma unroll
    for (int off = 16; off > 0; off >>= 1)
        local += __shfl_down_sync(0xFFFFFFFFu, local, off);
    if ((threadIdx.x & 31) == 0 && local)
        atomicAdd(&g_count[b], local);
}

// ---------------------------------------------------------------------------
// Kernel 2: pure-store re-zero of the histogram for the next replay +
// output expansion + counter reset (last x-CTA per batch).
// grid (64, 64) x 256 thr.
// ---------------------------------------------------------------------------
__global__ void dm2d_zero_out_kernel(float* __restrict__ out) {
    const int b = blockIdx.y;
    uint4* __restrict__ hist4 =
        reinterpret_cast<uint4*>(g_hist + (size_t)b * HWORDS_PER_BATCH);

    const int tid = blockIdx.x * 256 + threadIdx.x;   // 0..16383
    const uint4 zero4 = make_uint4(0u, 0u, 0u, 0u);
    #pragma unroll
    for (int u = 0; u < 4; u++)
        hist4[tid + u * 16384] = zero4;               // pure stores, stay L2-dirty

    if (blockIdx.x == 63) {
        const int K = (int)g_count[b];                // from K1 (launch-ordered)
        float* ob = out + (size_t)b * TOPK;
        #pragma unroll
        for (int u = 0; u < TOPK / 256; u++) {
            int i = u * 256 + threadIdx.x;
            ob[i] = (i < K) ? 1.0f : 0.0f;
        }
        __syncthreads();                              // all reads of K done
        if (threadIdx.x == 0) g_count[b] = 0u;        // reset for next replay
    }
}

extern "C" void kernel_launch(void* const* d_in, const int* in_sizes, int n_in,
                              void* d_out, int out_size) {
    (void)in_sizes; (void)n_in; (void)out_size;
    const float4* pcd = reinterpret_cast<const float4*>(d_in[0]);
    float* out = reinterpret_cast<float*>(d_out);

    dim3 grid(64, NBATCH);
    dm2d_hist_kernel<<<grid, 256>>>(pcd);
    dm2d_zero_out_kernel<<<grid, 256>>>(out);
}

// round 7
// speedup vs baseline: 1.2803x; 1.2803x over previous
#include <cuda_runtime.h>
#include <cstdint>

// DeepMapping2D occupancy_generation, GB300 sm_103a.  Round 7.
//
//   output[b] = K_b ones then zeros, K_b = #bins with count >= 53.
//   Min-shift is a bin bijection -> K_b shift-invariant -> no min pass.
//
// Validated model:
//   * scatter is pinned at the LTS sector-RMW cap: 16.7M x ~64B ~= 1.07GB
//     ~= 94us. REDG only -- R6 proved returning values (ATOMG) adds ~45%
//     sector traffic (+44us). Extra per-thread MLP hurts occupancy (R5).
//   * read-only count (~9us) + pure-store zero (+out, 11.7us) are each at
//     their L2-traffic floors; fusing load+store on the same lines is
//     poison (R3/R4: ~127us).
// R7 = best measured variant of each component, composed:
//   hist(R4 shape, REDG) -> count(read-only) -> zero+out(pure stores).

#define NBATCH  64
#define NPTS    262144
#define TOPK    5120
#define GZ_LOG2 10
#define BINS_PER_BATCH   (1024u * 1024u)          // 1M u8 bins / batch
#define HWORDS_PER_BATCH (BINS_PER_BATCH / 4)     // 256K u32 / batch

__device__ unsigned int g_hist[(size_t)NBATCH * HWORDS_PER_BATCH];  // 64 MB, load-zeroed
__device__ unsigned int g_count[NBATCH];                            // load-zeroed

// ---------------------------------------------------------------------------
// Kernel 1: histogram scatter, RED-only (fire-and-forget byte adds).
// grid (64, 64) x 256 thr; grid-stride, unroll 4. Measured 93.9us (R4).
// ---------------------------------------------------------------------------
__global__ void dm2d_hist_kernel(const float4* __restrict__ pcd) {
    const int b = blockIdx.y;
    unsigned int* __restrict__ hist = g_hist + (size_t)b * HWORDS_PER_BATCH;
    const float4* __restrict__ base = pcd + (size_t)b * (NPTS / 2);

    const int tid    = blockIdx.x * blockDim.x + threadIdx.x;
    const int stride = gridDim.x * blockDim.x;

    #pragma unroll 4
    for (int i = tid; i < NPTS / 2; i += stride) {
        float4 p = __ldcs(&base[i]);   // two points: (x0,z0,x1,z1); evict-first

        // jnp.round = round-half-to-even == rintf under default RN mode.
        unsigned x0 = (unsigned)(int)rintf(1000.0f * p.x);
        unsigned z0 = (unsigned)(int)rintf(1000.0f * p.y);
        unsigned x1 = (unsigned)(int)rintf(1000.0f * p.z);
        unsigned z1 = (unsigned)(int)rintf(1000.0f * p.w);

        unsigned i0 = (x0 << GZ_LOG2) | z0;
        unsigned i1 = (x1 << GZ_LOG2) | z1;

        // fire-and-forget byte increments (return unused -> REDG)
        atomicAdd(&hist[i0 >> 2], 1u << ((i0 & 3u) << 3));
        atomicAdd(&hist[i1 >> 2], 1u << ((i1 & 3u) << 3));
    }
}

// ---------------------------------------------------------------------------
// Kernel 2: count bins >= 53 per batch. READ-ONLY over the L2-resident hist.
// grid (64, 64) x 256 thr; 4 uint4 = 64 bins per thread. Measured ~9us.
// ---------------------------------------------------------------------------
__global__ void dm2d_count_kernel() {
    const int b = blockIdx.y;
    const uint4* __restrict__ hist4 =
        reinterpret_cast<const uint4*>(g_hist + (size_t)b * HWORDS_PER_BATCH);

    const int tid = blockIdx.x * 256 + threadIdx.x;   // 0..16383

    unsigned int cnt = 0;
    #pragma unroll
    for (int u = 0; u < 4; u++) {
        uint4 w = hist4[tid + u * 16384];
        cnt += __popc(__vcmpgeu4(w.x, 0x35353535u) & 0x01010101u);
        cnt += __popc(__vcmpgeu4(w.y, 0x35353535u) & 0x01010101u);
        cnt += __popc(__vcmpgeu4(w.z, 0x35353535u) & 0x01010101u);
        cnt += __popc(__vcmpgeu4(w.w, 0x35353535u) & 0x01010101u);
    }

    #pragma unroll
    for (int off = 16; off > 0; off >>= 1)
        cnt += __shfl_down_sync(0xFFFFFFFFu, cnt, off);
    if ((threadIdx.x & 31) == 0 && cnt)
        atomicAdd(&g_count[b], cnt);
}

// ---------------------------------------------------------------------------
// Kernel 3: pure-store re-zero of the histogram for the next replay +
// output expansion + counter reset (last x-CTA per batch). Measured 11.7us.
// grid (64, 64) x 256 thr.
// ---------------------------------------------------------------------------
__global__ void dm2d_zero_out_kernel(float* __restrict__ out) {
    const int b = blockIdx.y;
    uint4* __restrict__ hist4 =
        reinterpret_cast<uint4*>(g_hist + (size_t)b * HWORDS_PER_BATCH);

    const int tid = blockIdx.x * 256 + threadIdx.x;   // 0..16383
    const uint4 zero4 = make_uint4(0u, 0u, 0u, 0u);
    #pragma unroll
    for (int u = 0; u < 4; u++)
        hist4[tid + u * 16384] = zero4;               // pure stores, stay L2-dirty

    if (blockIdx.x == 63) {
        const int K = (int)g_count[b];                // from K2 (launch-ordered)
        float* ob = out + (size_t)b * TOPK;
        #pragma unroll
        for (int u = 0; u < TOPK / 256; u++) {
            int i = u * 256 + threadIdx.x;
            ob[i] = (i < K) ? 1.0f : 0.0f;
        }
        __syncthreads();                              // all reads of K done
        if (threadIdx.x == 0) g_count[b] = 0u;        // reset for next replay
    }
}

extern "C" void kernel_launch(void* const* d_in, const int* in_sizes, int n_in,
                              void* d_out, int out_size) {
    (void)in_sizes; (void)n_in; (void)out_size;
    const float4* pcd = reinterpret_cast<const float4*>(d_in[0]);
    float* out = reinterpret_cast<float*>(d_out);

    dim3 grid(64, NBATCH);
    dm2d_hist_kernel<<<grid, 256>>>(pcd);
    dm2d_count_kernel<<<grid, 256>>>();
    dm2d_zero_out_kernel<<<grid, 256>>>(out);
}

// round 8
// speedup vs baseline: 1.2817x; 1.0011x over previous
#include <cuda_runtime.h>
#include <cstdint>

// DeepMapping2D occupancy_generation, GB300 sm_103a.  Round 8.
//
//   output[b] = K_b ones then zeros, K_b = #bins with count >= 53.
//   Min-shift is a bin bijection -> K_b shift-invariant -> no min pass.
//
// Validated model (R4-R7):
//   * hist is pinned at the LTS sector-RMW cap (~1.07GB traffic ~= 95us).
//     REDG only; no return values (R6: +44us); no extra MLP (R5: occ drop).
//     hist kernel below is byte-identical to the R7 best -- DO NOT TOUCH.
//   * aux kernels are NOT bandwidth-bound (R6 ncu: L2 49%, issue 5.5%) ->
//     retune shapes: count gets fewer/longer CTAs, zero gets more CTAs
//     with shorter store chains.

#define NBATCH  64
#define NPTS    262144
#define TOPK    5120
#define GZ_LOG2 10
#define BINS_PER_BATCH   (1024u * 1024u)          // 1M u8 bins / batch
#define HWORDS_PER_BATCH (BINS_PER_BATCH / 4)     // 256K u32 / batch

__device__ unsigned int g_hist[(size_t)NBATCH * HWORDS_PER_BATCH];  // 64 MB, load-zeroed
__device__ unsigned int g_count[NBATCH];                            // load-zeroed

// ---------------------------------------------------------------------------
// Kernel 1: histogram scatter, RED-only (fire-and-forget byte adds).
// grid (64, 64) x 256 thr; grid-stride, unroll 4. Measured 93.9-95.4us.
// ---------------------------------------------------------------------------
__global__ void dm2d_hist_kernel(const float4* __restrict__ pcd) {
    const int b = blockIdx.y;
    unsigned int* __restrict__ hist = g_hist + (size_t)b * HWORDS_PER_BATCH;
    const float4* __restrict__ base = pcd + (size_t)b * (NPTS / 2);

    const int tid    = blockIdx.x * blockDim.x + threadIdx.x;
    const int stride = gridDim.x * blockDim.x;

    #pragma unroll 4
    for (int i = tid; i < NPTS / 2; i += stride) {
        float4 p = __ldcs(&base[i]);   // two points: (x0,z0,x1,z1); evict-first

        // jnp.round = round-half-to-even == rintf under default RN mode.
        unsigned x0 = (unsigned)(int)rintf(1000.0f * p.x);
        unsigned z0 = (unsigned)(int)rintf(1000.0f * p.y);
        unsigned x1 = (unsigned)(int)rintf(1000.0f * p.z);
        unsigned z1 = (unsigned)(int)rintf(1000.0f * p.w);

        unsigned i0 = (x0 << GZ_LOG2) | z0;
        unsigned i1 = (x1 << GZ_LOG2) | z1;

        // fire-and-forget byte increments (return unused -> REDG)
        atomicAdd(&hist[i0 >> 2], 1u << ((i0 & 3u) << 3));
        atomicAdd(&hist[i1 >> 2], 1u << ((i1 & 3u) << 3));
    }
}

// ---------------------------------------------------------------------------
// Kernel 2: count bins >= 53 per batch. READ-ONLY over the L2-resident hist.
// grid (32, 64) x 256 thr; 8 uint4 = 128 bins per thread (longer runs,
// fewer CTAs, tail amortized).
// ---------------------------------------------------------------------------
__global__ void dm2d_count_kernel() {
    const int b = blockIdx.y;
    const uint4* __restrict__ hist4 =
        reinterpret_cast<const uint4*>(g_hist + (size_t)b * HWORDS_PER_BATCH);

    const int tid = blockIdx.x * 256 + threadIdx.x;   // 0..8191

    unsigned int cnt = 0;
    #pragma unroll
    for (int u = 0; u < 8; u++) {
        uint4 w = hist4[tid + u * 8192];
        cnt += __popc(__vcmpgeu4(w.x, 0x35353535u) & 0x01010101u);
        cnt += __popc(__vcmpgeu4(w.y, 0x35353535u) & 0x01010101u);
        cnt += __popc(__vcmpgeu4(w.z, 0x35353535u) & 0x01010101u);
        cnt += __popc(__vcmpgeu4(w.w, 0x35353535u) & 0x01010101u);
    }

    #pragma unroll
    for (int off = 16; off > 0; off >>= 1)
        cnt += __shfl_down_sync(0xFFFFFFFFu, cnt, off);
    if ((threadIdx.x & 31) == 0 && cnt)
        atomicAdd(&g_count[b], cnt);
}

// ---------------------------------------------------------------------------
// Kernel 3: pure-store re-zero of the histogram for the next replay +
// output expansion + counter reset. grid (128, 64) x 256 thr; 2 uint4
// stores per thread (more CTA-level store parallelism -- R6 ncu showed no
// bandwidth cap at 4-stores/thread).
// ---------------------------------------------------------------------------
__global__ void dm2d_zero_out_kernel(float* __restrict__ out) {
    const int b = blockIdx.y;
    uint4* __restrict__ hist4 =
        reinterpret_cast<uint4*>(g_hist + (size_t)b * HWORDS_PER_BATCH);

    const int tid = blockIdx.x * 256 + threadIdx.x;   // 0..32767
    const uint4 zero4 = make_uint4(0u, 0u, 0u, 0u);
    hist4[tid]         = zero4;                       // pure stores, stay L2-dirty
    hist4[tid + 32768] = zero4;

    if (blockIdx.x == 127) {
        const int K = (int)g_count[b];                // from K2 (launch-ordered)
        float* ob = out + (size_t)b * TOPK;
        #pragma unroll
        for (int u = 0; u < TOPK / 256; u++) {
            int i = u * 256 + threadIdx.x;
            ob[i] = (i < K) ? 1.0f : 0.0f;
        }
        __syncthreads();                              // all reads of K done
        if (threadIdx.x == 0) g_count[b] = 0u;        // reset for next replay
    }
}

extern "C" void kernel_launch(void* const* d_in, const int* in_sizes, int n_in,
                              void* d_out, int out_size) {
    (void)in_sizes; (void)n_in; (void)out_size;
    const float4* pcd = reinterpret_cast<const float4*>(d_in[0]);
    float* out = reinterpret_cast<float*>(d_out);

    dm2d_hist_kernel<<<dim3(64, NBATCH), 256>>>(pcd);
    dm2d_count_kernel<<<dim3(32, NBATCH), 256>>>();
    dm2d_zero_out_kernel<<<dim3(128, NBATCH), 256>>>(out);
}